// round 1
// baseline (speedup 1.0000x reference)
#include <cuda_runtime.h>

typedef unsigned long long ull;

#define HDIM 1024
#define BDIM 64
#define TSTEPS 512
#define NCTA 128
#define RTHREADS 128
#define KC 64
#define HSTRIDE 66   // 64 + 2 pad floats -> odd 8B-unit stride, conflict-free LDS.64

// Scratch (device globals: allocation-free per harness rules)
__device__ float g_A[(size_t)TSTEPS * BDIM * HDIM];   // [T][B][H], x_t @ W_a^T + b_a
__device__ float g_h[2][BDIM * HDIM];                 // double-buffered hidden state
__device__ unsigned int g_bar_count;
__device__ unsigned int g_bar_gen;

// ---------------- packed f32x2 helpers ----------------
__device__ __forceinline__ ull ffma2(ull a, ull b, ull c) {
    ull d;
    asm("fma.rn.f32x2 %0, %1, %2, %3;" : "=l"(d) : "l"(a), "l"(b), "l"(c));
    return d;
}
__device__ __forceinline__ ull dup2(float a) {
    ull r;
    asm("mov.b64 %0, {%1, %1};" : "=l"(r) : "f"(a));
    return r;
}
__device__ __forceinline__ void unpack2(ull p, float& lo, float& hi) {
    asm("mov.b64 {%0, %1}, %2;" : "=f"(lo), "=f"(hi) : "l"(p));
}
__device__ __forceinline__ float sigf(float x) { return 1.0f / (1.0f + __expf(-x)); }

// ---------------- grid-wide barrier (all CTAs resident: grid=128 <= 148 SMs) ----------------
__device__ __forceinline__ void grid_barrier() {
    __syncthreads();
    if (threadIdx.x == 0) {
        __threadfence();  // make this CTA's global writes visible before arriving
        unsigned my = *((volatile unsigned int*)&g_bar_gen);
        __threadfence();
        unsigned prev = atomicAdd(&g_bar_count, 1u);
        if (prev == NCTA - 1) {
            atomicExch(&g_bar_count, 0u);
            __threadfence();
            atomicAdd(&g_bar_gen, 1u);
        } else {
            while (*((volatile unsigned int*)&g_bar_gen) == my) { __nanosleep(64); }
        }
    }
    __syncthreads();
}

// ---------------- Kernel 1: A[t][b][:] = x[b][t][:] @ W_a^T + b_a ----------------
// grid (HDIM/64, (B*T)/64), block 256, 64x64x32 tiles, fma2 pairs along N.
__global__ void __launch_bounds__(256) xa_gemm_kernel(
    const float* __restrict__ x, const float* __restrict__ Wa, const float* __restrict__ ba)
{
    __shared__ float a_s[32][64];
    __shared__ float b_s[32][64];
    const int tid   = threadIdx.x;
    const int rbase = blockIdx.y * 64;
    const int nbase = blockIdx.x * 64;
    const int m0 = (tid & 15) * 4;
    const int n0 = (tid >> 4) * 4;

    ull acc[4][2];
#pragma unroll
    for (int i = 0; i < 4; i++) { acc[i][0] = 0ull; acc[i][1] = 0ull; }

    for (int kc = 0; kc < HDIM; kc += 32) {
        __syncthreads();
#pragma unroll
        for (int l = tid; l < 512; l += 256) {
            int row = l >> 3, c4 = l & 7;
            float4 v = *(const float4*)(x + (size_t)(rbase + row) * HDIM + kc + c4 * 4);
            a_s[c4*4+0][row] = v.x; a_s[c4*4+1][row] = v.y;
            a_s[c4*4+2][row] = v.z; a_s[c4*4+3][row] = v.w;
            float4 w = *(const float4*)(Wa + (size_t)(nbase + row) * HDIM + kc + c4 * 4);
            b_s[c4*4+0][row] = w.x; b_s[c4*4+1][row] = w.y;
            b_s[c4*4+2][row] = w.z; b_s[c4*4+3][row] = w.w;
        }
        __syncthreads();
#pragma unroll
        for (int k = 0; k < 32; k++) {
            float4 av = *(const float4*)&a_s[k][m0];
            ull bp0 = *(const ull*)&b_s[k][n0];
            ull bp1 = *(const ull*)&b_s[k][n0 + 2];
            ull d;
            d = dup2(av.x); acc[0][0]=ffma2(d,bp0,acc[0][0]); acc[0][1]=ffma2(d,bp1,acc[0][1]);
            d = dup2(av.y); acc[1][0]=ffma2(d,bp0,acc[1][0]); acc[1][1]=ffma2(d,bp1,acc[1][1]);
            d = dup2(av.z); acc[2][0]=ffma2(d,bp0,acc[2][0]); acc[2][1]=ffma2(d,bp1,acc[2][1]);
            d = dup2(av.w); acc[3][0]=ffma2(d,bp0,acc[3][0]); acc[3][1]=ffma2(d,bp1,acc[3][1]);
        }
    }
#pragma unroll
    for (int i = 0; i < 4; i++) {
        int r  = rbase + m0 + i;
        int bb = r >> 9;       // x is [B][T][H] -> row = b*512 + t
        int tt = r & 511;
        float* orow = g_A + ((size_t)tt * BDIM + bb) * HDIM + nbase;
#pragma unroll
        for (int j = 0; j < 2; j++) {
            float lo, hi; unpack2(acc[i][j], lo, hi);
            int n = n0 + j * 2;
            orow[n]     = lo + ba[nbase + n];
            orow[n + 1] = hi + ba[nbase + n + 1];
        }
    }
}

// ---------------- Kernel 2: persistent recurrence ----------------
// 128 CTAs x 128 threads. CTA owns 8 h-columns; 24 weight rows (W_mu/Wg_mu/Wg_a)
// live in smem for the whole kernel. Thread tile: b in {bg, bg+32}, n in {ng, ng+4},
// all 3 gates -> 12 fma2 accumulators, k-packed pairs.
__global__ void __launch_bounds__(RTHREADS, 1) recur_kernel(
    const float* __restrict__ Wmu,  const float* __restrict__ bmu,
    const float* __restrict__ Wgmu, const float* __restrict__ bgmu,
    const float* __restrict__ Wga,  const float* __restrict__ bga,
    float* __restrict__ out)
{
    extern __shared__ float smem[];
    float* w_s = smem;                  // 24 * 1024 floats
    float* h_s = smem + 24 * HDIM;      // 2 * 64 * HSTRIDE floats (double-buffered chunk)

    const int tid = threadIdx.x;
    const int cta = blockIdx.x;
    const int bg  = tid & 31;
    const int ng  = tid >> 5;           // 0..3; whole warp shares ng -> broadcast w loads
    const int nb  = cta * 8;

    // Stage this CTA's 24 weight rows into smem (resident for all 512 steps).
    for (int idx = tid; idx < 24 * 256; idx += RTHREADS) {
        int row = idx >> 8, c4 = idx & 255;
        int i = row / 3, g = row - i * 3;   // row = n_local*3 + gate
        const float* src = (g == 0 ? Wmu : (g == 1 ? Wgmu : Wga)) + (size_t)(nb + i) * HDIM + c4 * 4;
        *(float4*)&w_s[row * HDIM + c4 * 4] = *(const float4*)src;
    }
    // h0 = 0
    for (int idx = tid; idx < 512; idx += RTHREADS)
        g_h[0][cta * 512 + idx] = 0.0f;

    const int na  = nb + ng, nbn = nb + ng + 4;
    const float bmu0 = bmu[na],  bmu1 = bmu[nbn];
    const float bgm0 = bgmu[na], bgm1 = bgmu[nbn];
    const float bga0 = bga[na],  bga1 = bga[nbn];

    const float* w0 = w_s + (ng * 3) * HDIM;
    const float* w1 = w_s + ((ng + 4) * 3) * HDIM;

    grid_barrier();  // weights staged (via its syncthreads) + h zeroed everywhere

    for (int t = 0; t < TSTEPS; t++) {
        const float* hcur  = g_h[t & 1];
        float*       hnext = g_h[(t + 1) & 1];

        ull acc[12];
#pragma unroll
        for (int i = 0; i < 12; i++) acc[i] = 0ull;

        // Register-staged prefetch of chunk 0 (ld.global.cg: coherent, skips L1)
        float4 r[8];
#pragma unroll
        for (int j = 0; j < 8; j++) {
            int idx = tid + j * RTHREADS;
            r[j] = __ldcg((const float4*)(hcur + (idx >> 4) * HDIM + (idx & 15) * 4));
        }

        for (int c = 0; c < 16; c++) {
            float* buf = h_s + (c & 1) * (64 * HSTRIDE);
            __syncthreads();
#pragma unroll
            for (int j = 0; j < 8; j++) {
                int idx = tid + j * RTHREADS;
                float* p = buf + (idx >> 4) * HSTRIDE + (idx & 15) * 4;
                *(float2*)p       = make_float2(r[j].x, r[j].y);
                *(float2*)(p + 2) = make_float2(r[j].z, r[j].w);
            }
            __syncthreads();
            if (c < 15) {  // issue next chunk's loads; they complete under the compute below
#pragma unroll
                for (int j = 0; j < 8; j++) {
                    int idx = tid + j * RTHREADS;
                    r[j] = __ldcg((const float4*)(hcur + (idx >> 4) * HDIM + (c + 1) * KC + (idx & 15) * 4));
                }
            }
            const float* hp0 = buf + bg * HSTRIDE;
            const float* hp1 = buf + (bg + 32) * HSTRIDE;
            const float* wc0 = w0 + c * KC;
            const float* wc1 = w1 + c * KC;
#pragma unroll 8
            for (int kk = 0; kk < KC; kk += 2) {
                ull h0 = *(const ull*)(hp0 + kk);
                ull h1 = *(const ull*)(hp1 + kk);
#pragma unroll
                for (int g = 0; g < 3; g++) {
                    ull wa = *(const ull*)(wc0 + g * HDIM + kk);   // warp-uniform broadcast
                    ull wb = *(const ull*)(wc1 + g * HDIM + kk);
                    acc[g]     = ffma2(h0, wa, acc[g]);
                    acc[3 + g] = ffma2(h1, wa, acc[3 + g]);
                    acc[6 + g] = ffma2(h0, wb, acc[6 + g]);
                    acc[9 + g] = ffma2(h1, wb, acc[9 + g]);
                }
            }
        }

        // Epilogue: 4 h-outputs per thread
#pragma unroll
        for (int q = 0; q < 4; q++) {
            int bb   = (q & 1) ? (bg + 32) : bg;
            int nn   = (q >> 1) ? nbn : na;
            int base = (q & 1) * 3 + (q >> 1) * 6;
            float lo, hi;
            unpack2(acc[base + 0], lo, hi); float dmu = lo + hi;
            unpack2(acc[base + 1], lo, hi); float dgm = lo + hi;
            unpack2(acc[base + 2], lo, hi); float dga = lo + hi;
            float av = __ldcg(&g_A[((size_t)t * BDIM + bb) * HDIM + nn]);
            float bm   = (q >> 1) ? bmu1 : bmu0;
            float bgmv = (q >> 1) ? bgm1 : bgm0;
            float bgav = (q >> 1) ? bga1 : bga0;
            float hv = (dmu + bm) * sigf(dgm + bgmv) + av * sigf(dga + bgav);
            __stcg(&hnext[bb * HDIM + nn], hv);
            if (t == TSTEPS - 1) out[bb * HDIM + nn] = hv;
        }
        grid_barrier();
    }
}

// ---------------- launch ----------------
extern "C" void kernel_launch(void* const* d_in, const int* in_sizes, int n_in,
                              void* d_out, int out_size) {
    const float* x    = (const float*)d_in[0];
    const float* Wmu  = (const float*)d_in[1];
    const float* bmu  = (const float*)d_in[2];
    const float* Wgmu = (const float*)d_in[3];
    const float* bgmu = (const float*)d_in[4];
    const float* Wa   = (const float*)d_in[5];
    const float* ba   = (const float*)d_in[6];
    const float* Wga  = (const float*)d_in[7];
    const float* bga  = (const float*)d_in[8];
    float* out = (float*)d_out;

    dim3 grid_pc(HDIM / 64, (BDIM * TSTEPS) / 64);   // x fast dim = N blocks for L2 reuse
    xa_gemm_kernel<<<grid_pc, 256>>>(x, Wa, ba);

    const size_t smem_bytes = (size_t)(24 * HDIM + 2 * 64 * HSTRIDE) * sizeof(float);  // ~132 KB
    cudaFuncSetAttribute(recur_kernel, cudaFuncAttributeMaxDynamicSharedMemorySize, (int)smem_bytes);
    recur_kernel<<<NCTA, RTHREADS, smem_bytes>>>(Wmu, bmu, Wgmu, bgmu, Wga, bga, out);
}

// round 3
// speedup vs baseline: 1.6164x; 1.6164x over previous
#include <cuda_runtime.h>
#include <cuda_bf16.h>
#include <cstdint>

typedef unsigned long long ull;
typedef unsigned int u32;

#define HDIM 1024
#define BDIM 64
#define TSTEPS 512
#define NCTA 128
#define NB 8              // n columns per CTA
#define THREADS 512
#define KCH 128           // K per h chunk
#define NCHUNK 8

// ---- smem offsets (relative to 1024B-aligned base) ----
#define OFF_WHI 0                      // 24*1024*2 = 49152
#define OFF_WLO 49152
#define OFF_H   98304                  // + buf*32768 + part*16384 (part0=hi, part1=lo)
#define OFF_D   163840                 // 64*26 floats = 6656
#define SMEM_USED 170496
#define SMEM_TOTAL (SMEM_USED + 1024)
#define DS_STRIDE 26

// ---- device scratch ----
__device__ float g_A[(size_t)TSTEPS * BDIM * HDIM];     // [T][B][H] = x W_a^T + b_a
__device__ __nv_bfloat16 g_hh[2][BDIM * HDIM];          // h hi, double-buffered
__device__ __nv_bfloat16 g_hl[2][BDIM * HDIM];          // h lo
__device__ unsigned int g_bar_count;
__device__ unsigned int g_bar_gen;

// ======================= helpers =======================
__device__ __forceinline__ u32 smem_u32(const void* p) {
    u32 a;
    asm("{ .reg .u64 t; cvta.to.shared.u64 t, %1; cvt.u32.u64 %0, t; }" : "=r"(a) : "l"(p));
    return a;
}
__device__ __forceinline__ void ldsm_x4(u32 a, u32& r0, u32& r1, u32& r2, u32& r3) {
    asm volatile("ldmatrix.sync.aligned.m8n8.x4.shared.b16 {%0,%1,%2,%3}, [%4];"
                 : "=r"(r0), "=r"(r1), "=r"(r2), "=r"(r3) : "r"(a));
}
__device__ __forceinline__ void ldsm_x2(u32 a, u32& r0, u32& r1) {
    asm volatile("ldmatrix.sync.aligned.m8n8.x2.shared.b16 {%0,%1}, [%2];"
                 : "=r"(r0), "=r"(r1) : "r"(a));
}
__device__ __forceinline__ void mma_bf16(float* c, u32 a0, u32 a1, u32 a2, u32 a3, u32 b0, u32 b1) {
    asm volatile(
        "mma.sync.aligned.m16n8k16.row.col.f32.bf16.bf16.f32 "
        "{%0,%1,%2,%3}, {%4,%5,%6,%7}, {%8,%9}, {%0,%1,%2,%3};"
        : "+f"(c[0]), "+f"(c[1]), "+f"(c[2]), "+f"(c[3])
        : "r"(a0), "r"(a1), "r"(a2), "r"(a3), "r"(b0), "r"(b1));
}
__device__ __forceinline__ unsigned short f2bf(float f) { return __bfloat16_as_ushort(__float2bfloat16(f)); }
__device__ __forceinline__ float bf2f(unsigned short s) { return __bfloat162float(__ushort_as_bfloat16(s)); }
__device__ __forceinline__ float sigf(float x) { return 1.0f / (1.0f + __expf(-x)); }
__device__ __forceinline__ ull ffma2(ull a, ull b, ull c) {
    ull d; asm("fma.rn.f32x2 %0, %1, %2, %3;" : "=l"(d) : "l"(a), "l"(b), "l"(c)); return d;
}
__device__ __forceinline__ ull dup2(float a) {
    ull r; asm("mov.b64 %0, {%1, %1};" : "=l"(r) : "f"(a)); return r;
}
__device__ __forceinline__ void unpack2(ull p, float& lo, float& hi) {
    asm("mov.b64 {%0, %1}, %2;" : "=f"(lo), "=f"(hi) : "l"(p));
}

// ---- grid-wide barrier (128 CTAs, all resident) ----
__device__ __forceinline__ void grid_barrier() {
    __syncthreads();
    if (threadIdx.x == 0) {
        __threadfence();
        unsigned my = *((volatile unsigned int*)&g_bar_gen);
        __threadfence();
        unsigned prev = atomicAdd(&g_bar_count, 1u);
        if (prev == NCTA - 1) {
            atomicExch(&g_bar_count, 0u);
            __threadfence();
            atomicAdd(&g_bar_gen, 1u);
        } else {
            while (*((volatile unsigned int*)&g_bar_gen) == my) { __nanosleep(64); }
        }
    }
    __syncthreads();
}

// ================= Kernel 1: A[t][b][:] = x[b][t][:] @ W_a^T + b_a =================
__global__ void __launch_bounds__(256) xa_gemm_kernel(
    const float* __restrict__ x, const float* __restrict__ Wa, const float* __restrict__ ba)
{
    __shared__ float a_s[32][64];
    __shared__ float b_s[32][64];
    const int tid   = threadIdx.x;
    const int rbase = blockIdx.y * 64;
    const int nbase = blockIdx.x * 64;
    const int m0 = (tid & 15) * 4;
    const int n0 = (tid >> 4) * 4;

    ull acc[4][2];
#pragma unroll
    for (int i = 0; i < 4; i++) { acc[i][0] = 0ull; acc[i][1] = 0ull; }

    for (int kc = 0; kc < HDIM; kc += 32) {
        __syncthreads();
#pragma unroll
        for (int l = tid; l < 512; l += 256) {
            int row = l >> 3, c4 = l & 7;
            float4 v = *(const float4*)(x + (size_t)(rbase + row) * HDIM + kc + c4 * 4);
            a_s[c4*4+0][row] = v.x; a_s[c4*4+1][row] = v.y;
            a_s[c4*4+2][row] = v.z; a_s[c4*4+3][row] = v.w;
            float4 w = *(const float4*)(Wa + (size_t)(nbase + row) * HDIM + kc + c4 * 4);
            b_s[c4*4+0][row] = w.x; b_s[c4*4+1][row] = w.y;
            b_s[c4*4+2][row] = w.z; b_s[c4*4+3][row] = w.w;
        }
        __syncthreads();
#pragma unroll
        for (int k = 0; k < 32; k++) {
            float4 av = *(const float4*)&a_s[k][m0];
            ull bp0 = *(const ull*)&b_s[k][n0];
            ull bp1 = *(const ull*)&b_s[k][n0 + 2];
            ull d;
            d = dup2(av.x); acc[0][0]=ffma2(d,bp0,acc[0][0]); acc[0][1]=ffma2(d,bp1,acc[0][1]);
            d = dup2(av.y); acc[1][0]=ffma2(d,bp0,acc[1][0]); acc[1][1]=ffma2(d,bp1,acc[1][1]);
            d = dup2(av.z); acc[2][0]=ffma2(d,bp0,acc[2][0]); acc[2][1]=ffma2(d,bp1,acc[2][1]);
            d = dup2(av.w); acc[3][0]=ffma2(d,bp0,acc[3][0]); acc[3][1]=ffma2(d,bp1,acc[3][1]);
        }
    }
#pragma unroll
    for (int i = 0; i < 4; i++) {
        int r  = rbase + m0 + i;
        int bb = r >> 9;       // x row = b*512 + t
        int tt = r & 511;
        float* orow = g_A + ((size_t)tt * BDIM + bb) * HDIM + nbase;
#pragma unroll
        for (int j = 0; j < 2; j++) {
            float lo, hi; unpack2(acc[i][j], lo, hi);
            int n = n0 + j * 2;
            orow[n]     = lo + ba[nbase + n];
            orow[n + 1] = hi + ba[nbase + n + 1];
        }
    }
}

// ================= Kernel 2: persistent mma.sync recurrence =================
__global__ void __launch_bounds__(THREADS, 1) recur_mma_kernel(
    const float* __restrict__ Wmu,  const float* __restrict__ bmu,
    const float* __restrict__ Wgmu, const float* __restrict__ bgmu,
    const float* __restrict__ Wga,  const float* __restrict__ bga,
    float* __restrict__ out)
{
    extern __shared__ char smem_raw[];
    u32 raw_base = smem_u32(smem_raw);
    u32 abase = (raw_base + 1023u) & ~1023u;
    char* sm = smem_raw + (abase - raw_base);

    const int tid = threadIdx.x;
    const int wid = tid >> 5;
    const int lan = tid & 31;
    const int cta = blockIdx.x;
    const int nb  = cta * NB;

    // ---- stage weights: r = g*8+nl (0..23), K=1024, bf16 hi/lo, SW128 swizzled ----
    // layout: byte = (k>>6)*3072 + g*1024 + (r&7)*128 + (k&63)*2 ; ^ ((r&7)<<4)
    for (int u = tid; u < 24 * 128; u += THREADS) {
        int r = u >> 7, k = (u & 127) * 8;
        int g = r >> 3, nl = r & 7;
        const float* wp = (g == 0 ? Wmu : (g == 1 ? Wgmu : Wga)) + (size_t)(nb + nl) * HDIM + k;
        float4 v0 = *(const float4*)wp;
        float4 v1 = *(const float4*)(wp + 4);
        float vv[8] = {v0.x, v0.y, v0.z, v0.w, v1.x, v1.y, v1.z, v1.w};
        u32 hw[4], lw[4];
#pragma unroll
        for (int i = 0; i < 4; i++) {
            unsigned short h0 = f2bf(vv[2*i]),   h1 = f2bf(vv[2*i+1]);
            unsigned short l0 = f2bf(vv[2*i]   - bf2f(h0));
            unsigned short l1 = f2bf(vv[2*i+1] - bf2f(h1));
            hw[i] = (u32)h0 | ((u32)h1 << 16);
            lw[i] = (u32)l0 | ((u32)l1 << 16);
        }
        u32 byte = (u32)(k >> 6) * 3072u + (u32)g * 1024u + (u32)(r & 7) * 128u + (u32)(k & 63) * 2u;
        u32 sw = byte ^ ((u32)(r & 7) << 4);
        *(uint4*)(sm + OFF_WHI + sw) = make_uint4(hw[0], hw[1], hw[2], hw[3]);
        *(uint4*)(sm + OFF_WLO + sw) = make_uint4(lw[0], lw[1], lw[2], lw[3]);
    }

    // ---- h0 = 0 (this CTA's columns, buffer 0) ----
    if (tid < 64) {
        uint4 z = make_uint4(0, 0, 0, 0);
        *(uint4*)&g_hh[0][tid * HDIM + nb] = z;
        *(uint4*)&g_hl[0][tid * HDIM + nb] = z;
    }

    // per-thread h-chunk staging offsets (constant across steps)
    // u in 0..1023 uint4 per part; row = u>>4, kcol = (u&15)*8
    const int u0 = tid, u1 = tid + 512;
    const int row0 = u0 >> 4, kc0 = (u0 & 15) * 8;
    const int row1 = u1 >> 4, kc1 = (u1 & 15) * 8;
    const u32 sw0 = ((u32)(kc0 >> 6) * 8192u + (u32)(row0 >> 3) * 1024u +
                     (u32)(row0 & 7) * 128u + (u32)(kc0 & 63) * 2u) ^ ((u32)(row0 & 7) << 4);
    const u32 sw1 = ((u32)(kc1 >> 6) * 8192u + (u32)(row1 >> 3) * 1024u +
                     (u32)(row1 & 7) * 128u + (u32)(kc1 & 63) * 2u) ^ ((u32)(row1 & 7) << 4);
    const int src0 = row0 * HDIM + kc0;
    const int src1 = row1 * HDIM + kc1;

    // mma warp per-lane ldmatrix offsets
    const int mt = wid;                     // m-tile for warps 0..3
    const int arow = mt * 16 + (lan & 15);
    const int aklp = (lan >> 4) * 8;
    const int b7   = lan & 7;
    const int bklp = ((lan >> 3) & 1) * 8;
    u32 a_off[8], b_inn[8];
#pragma unroll
    for (int kl = 0; kl < 8; kl++) {
        int kcol = kl * 16 + aklp;
        a_off[kl] = ((u32)(kcol >> 6) * 8192u + (u32)(arow >> 3) * 1024u +
                     (u32)(arow & 7) * 128u + (u32)(kcol & 63) * 2u) ^ ((u32)(arow & 7) << 4);
        int bc = kl * 16 + bklp;            // within-128 part of b column
        b_inn[kl] = ((u32)(bc >> 6) * 3072u + (u32)b7 * 128u + (u32)(bc & 63) * 2u) ^ ((u32)b7 << 4);
    }
    const u32 hsb  = abase + OFF_H;
    const u32 whib = abase + OFF_WHI;
    const u32 wlob = abase + OFF_WLO;
    float* ds = (float*)(sm + OFF_D);

    // biases
    float cb_mu[8], cb_gm[8], cb_ga[8];
#pragma unroll
    for (int i = 0; i < 8; i++) {
        cb_mu[i] = bmu[nb + i]; cb_gm[i] = bgmu[nb + i]; cb_ga[i] = bga[nb + i];
    }

    grid_barrier();     // weights staged everywhere, h0 zeroed

    for (int t = 0; t < TSTEPS; t++) {
        const __nv_bfloat16* hh = g_hh[t & 1];
        const __nv_bfloat16* hl = g_hl[t & 1];

        float c[12];
#pragma unroll
        for (int i = 0; i < 12; i++) c[i] = 0.0f;

        // prefetch chunk 0
        uint4 ph0 = __ldcg((const uint4*)(hh + src0));
        uint4 ph1 = __ldcg((const uint4*)(hh + src1));
        uint4 pl0 = __ldcg((const uint4*)(hl + src0));
        uint4 pl1 = __ldcg((const uint4*)(hl + src1));

        for (int kc = 0; kc < NCHUNK; kc++) {
            const int buf = kc & 1;
            char* hb = sm + OFF_H + buf * 32768;
            __syncthreads();                        // buf free
            *(uint4*)(hb + sw0)         = ph0;
            *(uint4*)(hb + sw1)         = ph1;
            *(uint4*)(hb + 16384 + sw0) = pl0;
            *(uint4*)(hb + 16384 + sw1) = pl1;
            __syncthreads();                        // staging visible
            if (kc < NCHUNK - 1) {                  // prefetch next (latency hides under mma)
                int so = (kc + 1) * KCH;
                ph0 = __ldcg((const uint4*)(hh + src0 + so));
                ph1 = __ldcg((const uint4*)(hh + src1 + so));
                pl0 = __ldcg((const uint4*)(hl + src0 + so));
                pl1 = __ldcg((const uint4*)(hl + src1 + so));
            }
            if (wid < 4) {
                const u32 ahb = hsb + buf * 32768;
                const u32 alb = ahb + 16384;
                const u32 wko = (u32)kc * 6144u;
#pragma unroll
                for (int kl = 0; kl < 8; kl++) {
                    u32 ah0, ah1, ah2, ah3, al0, al1, al2, al3;
                    ldsm_x4(ahb + a_off[kl], ah0, ah1, ah2, ah3);
                    ldsm_x4(alb + a_off[kl], al0, al1, al2, al3);
#pragma unroll
                    for (int g = 0; g < 3; g++) {
                        u32 wo = wko + (u32)g * 1024u + b_inn[kl];
                        u32 bh0, bh1, bl0, bl1;
                        ldsm_x2(whib + wo, bh0, bh1);
                        ldsm_x2(wlob + wo, bl0, bl1);
                        mma_bf16(c + g * 4, ah0, ah1, ah2, ah3, bh0, bh1);
                        mma_bf16(c + g * 4, ah0, ah1, ah2, ah3, bl0, bl1);
                        mma_bf16(c + g * 4, al0, al1, al2, al3, bh0, bh1);
                    }
                }
            }
        }

        __syncthreads();
        // ---- exchange D fragments via smem ----
        if (wid < 4) {
            int r0 = mt * 16 + (lan >> 2);
            int cc = (lan & 3) * 2;
#pragma unroll
            for (int g = 0; g < 3; g++) {
                *(float2*)&ds[r0 * DS_STRIDE + g * 8 + cc]       = make_float2(c[g*4+0], c[g*4+1]);
                *(float2*)&ds[(r0 + 8) * DS_STRIDE + g * 8 + cc] = make_float2(c[g*4+2], c[g*4+3]);
            }
        }
        __syncthreads();

        // ---- epilogue: 64 threads, one per batch row ----
        if (tid < 64) {
            const float* drow = ds + tid * DS_STRIDE;
            const float* arow_p = g_A + ((size_t)t * BDIM + tid) * HDIM + nb;
            float4 a0 = __ldcg((const float4*)arow_p);
            float4 a1 = __ldcg((const float4*)(arow_p + 4));
            float av[8] = {a0.x, a0.y, a0.z, a0.w, a1.x, a1.y, a1.z, a1.w};
            float ov[8];
#pragma unroll
            for (int i = 0; i < 8; i++) {
                float mu = drow[i]      + cb_mu[i];
                float gm = drow[8 + i]  + cb_gm[i];
                float ga = drow[16 + i] + cb_ga[i];
                ov[i] = mu * sigf(gm) + av[i] * sigf(ga);
            }
            u32 hw[4], lw[4];
#pragma unroll
            for (int i = 0; i < 4; i++) {
                unsigned short h0 = f2bf(ov[2*i]),   h1 = f2bf(ov[2*i+1]);
                unsigned short l0 = f2bf(ov[2*i]   - bf2f(h0));
                unsigned short l1 = f2bf(ov[2*i+1] - bf2f(h1));
                hw[i] = (u32)h0 | ((u32)h1 << 16);
                lw[i] = (u32)l0 | ((u32)l1 << 16);
            }
            __stcg((uint4*)&g_hh[(t + 1) & 1][tid * HDIM + nb], make_uint4(hw[0], hw[1], hw[2], hw[3]));
            __stcg((uint4*)&g_hl[(t + 1) & 1][tid * HDIM + nb], make_uint4(lw[0], lw[1], lw[2], lw[3]));
            if (t == TSTEPS - 1) {
                *(float4*)(out + (size_t)tid * HDIM + nb)     = make_float4(ov[0], ov[1], ov[2], ov[3]);
                *(float4*)(out + (size_t)tid * HDIM + nb + 4) = make_float4(ov[4], ov[5], ov[6], ov[7]);
            }
        }
        grid_barrier();
    }
}

// ================= launch =================
extern "C" void kernel_launch(void* const* d_in, const int* in_sizes, int n_in,
                              void* d_out, int out_size) {
    const float* x    = (const float*)d_in[0];
    const float* Wmu  = (const float*)d_in[1];
    const float* bmu  = (const float*)d_in[2];
    const float* Wgmu = (const float*)d_in[3];
    const float* bgmu = (const float*)d_in[4];
    const float* Wa   = (const float*)d_in[5];
    const float* ba   = (const float*)d_in[6];
    const float* Wga  = (const float*)d_in[7];
    const float* bga  = (const float*)d_in[8];
    float* out = (float*)d_out;

    dim3 grid_pc(HDIM / 64, (BDIM * TSTEPS) / 64);
    xa_gemm_kernel<<<grid_pc, 256>>>(x, Wa, ba);

    cudaFuncSetAttribute(recur_mma_kernel, cudaFuncAttributeMaxDynamicSharedMemorySize, SMEM_TOTAL);
    recur_mma_kernel<<<NCTA, THREADS, SMEM_TOTAL>>>(Wmu, bmu, Wgmu, bgmu, Wga, bga, out);
}

// round 4
// speedup vs baseline: 1.6200x; 1.0022x over previous
#include <cuda_runtime.h>
#include <cuda_bf16.h>
#include <cstdint>

typedef unsigned long long ull;
typedef unsigned int u32;

#define HDIM 1024
#define BDIM 64
#define TSTEPS 512
#define NCTA 128
#define NB 8              // n columns per CTA
#define THREADS 512
#define KCH 128           // K per h chunk
#define NCHUNK 8

// ---- smem offsets (relative to 1024B-aligned base) ----
#define OFF_WHI 0                      // 24*1024*2 = 49152
#define OFF_WLO 49152
#define OFF_H   98304                  // + buf*32768 + part*16384 (part0=hi, part1=lo)
#define OFF_D   163840                 // 64*26 floats = 6656
#define SMEM_USED 170496
#define SMEM_TOTAL (SMEM_USED + 1024)
#define DS_STRIDE 26

// ---- device scratch ----
__device__ float g_A[(size_t)TSTEPS * BDIM * HDIM];     // [T][B][H] = x W_a^T + b_a
__device__ __nv_bfloat16 g_hh[2][BDIM * HDIM];          // h hi, double-buffered
__device__ __nv_bfloat16 g_hl[2][BDIM * HDIM];          // h lo
__device__ unsigned int g_bar_count;
__device__ unsigned int g_bar_gen;

// ======================= helpers =======================
__device__ __forceinline__ u32 smem_u32(const void* p) {
    u32 a;
    asm("{ .reg .u64 t; cvta.to.shared.u64 t, %1; cvt.u32.u64 %0, t; }" : "=r"(a) : "l"(p));
    return a;
}
__device__ __forceinline__ void ldsm_x4(u32 a, u32& r0, u32& r1, u32& r2, u32& r3) {
    asm volatile("ldmatrix.sync.aligned.m8n8.x4.shared.b16 {%0,%1,%2,%3}, [%4];"
                 : "=r"(r0), "=r"(r1), "=r"(r2), "=r"(r3) : "r"(a));
}
__device__ __forceinline__ void ldsm_x2(u32 a, u32& r0, u32& r1) {
    asm volatile("ldmatrix.sync.aligned.m8n8.x2.shared.b16 {%0,%1}, [%2];"
                 : "=r"(r0), "=r"(r1) : "r"(a));
}
__device__ __forceinline__ void mma_bf16(float* c, u32 a0, u32 a1, u32 a2, u32 a3, u32 b0, u32 b1) {
    asm volatile(
        "mma.sync.aligned.m16n8k16.row.col.f32.bf16.bf16.f32 "
        "{%0,%1,%2,%3}, {%4,%5,%6,%7}, {%8,%9}, {%0,%1,%2,%3};"
        : "+f"(c[0]), "+f"(c[1]), "+f"(c[2]), "+f"(c[3])
        : "r"(a0), "r"(a1), "r"(a2), "r"(a3), "r"(b0), "r"(b1));
}
__device__ __forceinline__ unsigned short f2bf(float f) { return __bfloat16_as_ushort(__float2bfloat16(f)); }
__device__ __forceinline__ float bf2f(unsigned short s) { return __bfloat162float(__ushort_as_bfloat16(s)); }
__device__ __forceinline__ float sigf(float x) { return 1.0f / (1.0f + __expf(-x)); }
__device__ __forceinline__ ull ffma2(ull a, ull b, ull c) {
    ull d; asm("fma.rn.f32x2 %0, %1, %2, %3;" : "=l"(d) : "l"(a), "l"(b), "l"(c)); return d;
}
__device__ __forceinline__ ull dup2(float a) {
    ull r; asm("mov.b64 %0, {%1, %1};" : "=l"(r) : "f"(a)); return r;
}
__device__ __forceinline__ void unpack2(ull p, float& lo, float& hi) {
    asm("mov.b64 {%0, %1}, %2;" : "=f"(lo), "=f"(hi) : "l"(p));
}

// ---- grid-wide barrier (128 CTAs, all resident) ----
__device__ __forceinline__ void grid_barrier() {
    __syncthreads();
    if (threadIdx.x == 0) {
        __threadfence();
        unsigned my = *((volatile unsigned int*)&g_bar_gen);
        __threadfence();
        unsigned prev = atomicAdd(&g_bar_count, 1u);
        if (prev == NCTA - 1) {
            atomicExch(&g_bar_count, 0u);
            __threadfence();
            atomicAdd(&g_bar_gen, 1u);
        } else {
            while (*((volatile unsigned int*)&g_bar_gen) == my) { __nanosleep(64); }
        }
    }
    __syncthreads();
}

// ================= Kernel 1: A[t][b][:] = x[b][t][:] @ W_a^T + b_a =================
__global__ void __launch_bounds__(256) xa_gemm_kernel(
    const float* __restrict__ x, const float* __restrict__ Wa, const float* __restrict__ ba)
{
    __shared__ float a_s[32][64];
    __shared__ float b_s[32][64];
    const int tid   = threadIdx.x;
    const int rbase = blockIdx.y * 64;
    const int nbase = blockIdx.x * 64;
    const int m0 = (tid & 15) * 4;
    const int n0 = (tid >> 4) * 4;

    ull acc[4][2];
#pragma unroll
    for (int i = 0; i < 4; i++) { acc[i][0] = 0ull; acc[i][1] = 0ull; }

    for (int kc = 0; kc < HDIM; kc += 32) {
        __syncthreads();
#pragma unroll
        for (int l = tid; l < 512; l += 256) {
            int row = l >> 3, c4 = l & 7;
            float4 v = *(const float4*)(x + (size_t)(rbase + row) * HDIM + kc + c4 * 4);
            a_s[c4*4+0][row] = v.x; a_s[c4*4+1][row] = v.y;
            a_s[c4*4+2][row] = v.z; a_s[c4*4+3][row] = v.w;
            float4 w = *(const float4*)(Wa + (size_t)(nbase + row) * HDIM + kc + c4 * 4);
            b_s[c4*4+0][row] = w.x; b_s[c4*4+1][row] = w.y;
            b_s[c4*4+2][row] = w.z; b_s[c4*4+3][row] = w.w;
        }
        __syncthreads();
#pragma unroll
        for (int k = 0; k < 32; k++) {
            float4 av = *(const float4*)&a_s[k][m0];
            ull bp0 = *(const ull*)&b_s[k][n0];
            ull bp1 = *(const ull*)&b_s[k][n0 + 2];
            ull d;
            d = dup2(av.x); acc[0][0]=ffma2(d,bp0,acc[0][0]); acc[0][1]=ffma2(d,bp1,acc[0][1]);
            d = dup2(av.y); acc[1][0]=ffma2(d,bp0,acc[1][0]); acc[1][1]=ffma2(d,bp1,acc[1][1]);
            d = dup2(av.z); acc[2][0]=ffma2(d,bp0,acc[2][0]); acc[2][1]=ffma2(d,bp1,acc[2][1]);
            d = dup2(av.w); acc[3][0]=ffma2(d,bp0,acc[3][0]); acc[3][1]=ffma2(d,bp1,acc[3][1]);
        }
    }
#pragma unroll
    for (int i = 0; i < 4; i++) {
        int r  = rbase + m0 + i;
        int bb = r >> 9;       // x row = b*512 + t
        int tt = r & 511;
        float* orow = g_A + ((size_t)tt * BDIM + bb) * HDIM + nbase;
#pragma unroll
        for (int j = 0; j < 2; j++) {
            float lo, hi; unpack2(acc[i][j], lo, hi);
            int n = n0 + j * 2;
            orow[n]     = lo + ba[nbase + n];
            orow[n + 1] = hi + ba[nbase + n + 1];
        }
    }
}

// ================= Kernel 2: persistent mma.sync recurrence =================
__global__ void __launch_bounds__(THREADS, 1) recur_mma_kernel(
    const float* __restrict__ Wmu,  const float* __restrict__ bmu,
    const float* __restrict__ Wgmu, const float* __restrict__ bgmu,
    const float* __restrict__ Wga,  const float* __restrict__ bga,
    float* __restrict__ out)
{
    extern __shared__ char smem_raw[];
    u32 raw_base = smem_u32(smem_raw);
    u32 abase = (raw_base + 1023u) & ~1023u;
    char* sm = smem_raw + (abase - raw_base);

    const int tid = threadIdx.x;
    const int wid = tid >> 5;
    const int lan = tid & 31;
    const int cta = blockIdx.x;
    const int nb  = cta * NB;

    // ---- stage weights: r = g*8+nl (0..23), K=1024, bf16 hi/lo, SW128 swizzled ----
    // layout: byte = (k>>6)*3072 + g*1024 + (r&7)*128 + (k&63)*2 ; ^ ((r&7)<<4)
    for (int u = tid; u < 24 * 128; u += THREADS) {
        int r = u >> 7, k = (u & 127) * 8;
        int g = r >> 3, nl = r & 7;
        const float* wp = (g == 0 ? Wmu : (g == 1 ? Wgmu : Wga)) + (size_t)(nb + nl) * HDIM + k;
        float4 v0 = *(const float4*)wp;
        float4 v1 = *(const float4*)(wp + 4);
        float vv[8] = {v0.x, v0.y, v0.z, v0.w, v1.x, v1.y, v1.z, v1.w};
        u32 hw[4], lw[4];
#pragma unroll
        for (int i = 0; i < 4; i++) {
            unsigned short h0 = f2bf(vv[2*i]),   h1 = f2bf(vv[2*i+1]);
            unsigned short l0 = f2bf(vv[2*i]   - bf2f(h0));
            unsigned short l1 = f2bf(vv[2*i+1] - bf2f(h1));
            hw[i] = (u32)h0 | ((u32)h1 << 16);
            lw[i] = (u32)l0 | ((u32)l1 << 16);
        }
        u32 byte = (u32)(k >> 6) * 3072u + (u32)g * 1024u + (u32)(r & 7) * 128u + (u32)(k & 63) * 2u;
        u32 sw = byte ^ ((u32)(r & 7) << 4);
        *(uint4*)(sm + OFF_WHI + sw) = make_uint4(hw[0], hw[1], hw[2], hw[3]);
        *(uint4*)(sm + OFF_WLO + sw) = make_uint4(lw[0], lw[1], lw[2], lw[3]);
    }

    // ---- h0 = 0 (this CTA's columns, buffer 0) ----
    if (tid < 64) {
        uint4 z = make_uint4(0, 0, 0, 0);
        *(uint4*)&g_hh[0][tid * HDIM + nb] = z;
        *(uint4*)&g_hl[0][tid * HDIM + nb] = z;
    }

    // per-thread h-chunk staging offsets (constant across steps)
    // u in 0..1023 uint4 per part; row = u>>4, kcol = (u&15)*8
    const int u0 = tid, u1 = tid + 512;
    const int row0 = u0 >> 4, kc0 = (u0 & 15) * 8;
    const int row1 = u1 >> 4, kc1 = (u1 & 15) * 8;
    const u32 sw0 = ((u32)(kc0 >> 6) * 8192u + (u32)(row0 >> 3) * 1024u +
                     (u32)(row0 & 7) * 128u + (u32)(kc0 & 63) * 2u) ^ ((u32)(row0 & 7) << 4);
    const u32 sw1 = ((u32)(kc1 >> 6) * 8192u + (u32)(row1 >> 3) * 1024u +
                     (u32)(row1 & 7) * 128u + (u32)(kc1 & 63) * 2u) ^ ((u32)(row1 & 7) << 4);
    const int src0 = row0 * HDIM + kc0;
    const int src1 = row1 * HDIM + kc1;

    // mma warp per-lane ldmatrix offsets
    const int mt = wid;                     // m-tile for warps 0..3
    const int arow = mt * 16 + (lan & 15);
    const int aklp = (lan >> 4) * 8;
    const int b7   = lan & 7;
    const int bklp = ((lan >> 3) & 1) * 8;
    u32 a_off[8], b_inn[8];
#pragma unroll
    for (int kl = 0; kl < 8; kl++) {
        int kcol = kl * 16 + aklp;
        a_off[kl] = ((u32)(kcol >> 6) * 8192u + (u32)(arow >> 3) * 1024u +
                     (u32)(arow & 7) * 128u + (u32)(kcol & 63) * 2u) ^ ((u32)(arow & 7) << 4);
        int bc = kl * 16 + bklp;            // within-128 part of b column
        b_inn[kl] = ((u32)(bc >> 6) * 3072u + (u32)b7 * 128u + (u32)(bc & 63) * 2u) ^ ((u32)b7 << 4);
    }
    const u32 hsb  = abase + OFF_H;
    const u32 whib = abase + OFF_WHI;
    const u32 wlob = abase + OFF_WLO;
    float* ds = (float*)(sm + OFF_D);

    // biases
    float cb_mu[8], cb_gm[8], cb_ga[8];
#pragma unroll
    for (int i = 0; i < 8; i++) {
        cb_mu[i] = bmu[nb + i]; cb_gm[i] = bgmu[nb + i]; cb_ga[i] = bga[nb + i];
    }

    grid_barrier();     // weights staged everywhere, h0 zeroed

    for (int t = 0; t < TSTEPS; t++) {
        const __nv_bfloat16* hh = g_hh[t & 1];
        const __nv_bfloat16* hl = g_hl[t & 1];

        float c[12];
#pragma unroll
        for (int i = 0; i < 12; i++) c[i] = 0.0f;

        // prefetch chunk 0
        uint4 ph0 = __ldcg((const uint4*)(hh + src0));
        uint4 ph1 = __ldcg((const uint4*)(hh + src1));
        uint4 pl0 = __ldcg((const uint4*)(hl + src0));
        uint4 pl1 = __ldcg((const uint4*)(hl + src1));

        for (int kc = 0; kc < NCHUNK; kc++) {
            const int buf = kc & 1;
            char* hb = sm + OFF_H + buf * 32768;
            __syncthreads();                        // buf free
            *(uint4*)(hb + sw0)         = ph0;
            *(uint4*)(hb + sw1)         = ph1;
            *(uint4*)(hb + 16384 + sw0) = pl0;
            *(uint4*)(hb + 16384 + sw1) = pl1;
            __syncthreads();                        // staging visible
            if (kc < NCHUNK - 1) {                  // prefetch next (latency hides under mma)
                int so = (kc + 1) * KCH;
                ph0 = __ldcg((const uint4*)(hh + src0 + so));
                ph1 = __ldcg((const uint4*)(hh + src1 + so));
                pl0 = __ldcg((const uint4*)(hl + src0 + so));
                pl1 = __ldcg((const uint4*)(hl + src1 + so));
            }
            if (wid < 4) {
                const u32 ahb = hsb + buf * 32768;
                const u32 alb = ahb + 16384;
                const u32 wko = (u32)kc * 6144u;
#pragma unroll
                for (int kl = 0; kl < 8; kl++) {
                    u32 ah0, ah1, ah2, ah3, al0, al1, al2, al3;
                    ldsm_x4(ahb + a_off[kl], ah0, ah1, ah2, ah3);
                    ldsm_x4(alb + a_off[kl], al0, al1, al2, al3);
#pragma unroll
                    for (int g = 0; g < 3; g++) {
                        u32 wo = wko + (u32)g * 1024u + b_inn[kl];
                        u32 bh0, bh1, bl0, bl1;
                        ldsm_x2(whib + wo, bh0, bh1);
                        ldsm_x2(wlob + wo, bl0, bl1);
                        mma_bf16(c + g * 4, ah0, ah1, ah2, ah3, bh0, bh1);
                        mma_bf16(c + g * 4, ah0, ah1, ah2, ah3, bl0, bl1);
                        mma_bf16(c + g * 4, al0, al1, al2, al3, bh0, bh1);
                    }
                }
            }
        }

        __syncthreads();
        // ---- exchange D fragments via smem ----
        if (wid < 4) {
            int r0 = mt * 16 + (lan >> 2);
            int cc = (lan & 3) * 2;
#pragma unroll
            for (int g = 0; g < 3; g++) {
                *(float2*)&ds[r0 * DS_STRIDE + g * 8 + cc]       = make_float2(c[g*4+0], c[g*4+1]);
                *(float2*)&ds[(r0 + 8) * DS_STRIDE + g * 8 + cc] = make_float2(c[g*4+2], c[g*4+3]);
            }
        }
        __syncthreads();

        // ---- epilogue: 64 threads, one per batch row ----
        if (tid < 64) {
            const float* drow = ds + tid * DS_STRIDE;
            const float* arow_p = g_A + ((size_t)t * BDIM + tid) * HDIM + nb;
            float4 a0 = __ldcg((const float4*)arow_p);
            float4 a1 = __ldcg((const float4*)(arow_p + 4));
            float av[8] = {a0.x, a0.y, a0.z, a0.w, a1.x, a1.y, a1.z, a1.w};
            float ov[8];
#pragma unroll
            for (int i = 0; i < 8; i++) {
                float mu = drow[i]      + cb_mu[i];
                float gm = drow[8 + i]  + cb_gm[i];
                float ga = drow[16 + i] + cb_ga[i];
                ov[i] = mu * sigf(gm) + av[i] * sigf(ga);
            }
            u32 hw[4], lw[4];
#pragma unroll
            for (int i = 0; i < 4; i++) {
                unsigned short h0 = f2bf(ov[2*i]),   h1 = f2bf(ov[2*i+1]);
                unsigned short l0 = f2bf(ov[2*i]   - bf2f(h0));
                unsigned short l1 = f2bf(ov[2*i+1] - bf2f(h1));
                hw[i] = (u32)h0 | ((u32)h1 << 16);
                lw[i] = (u32)l0 | ((u32)l1 << 16);
            }
            __stcg((uint4*)&g_hh[(t + 1) & 1][tid * HDIM + nb], make_uint4(hw[0], hw[1], hw[2], hw[3]));
            __stcg((uint4*)&g_hl[(t + 1) & 1][tid * HDIM + nb], make_uint4(lw[0], lw[1], lw[2], lw[3]));
            if (t == TSTEPS - 1) {
                *(float4*)(out + (size_t)tid * HDIM + nb)     = make_float4(ov[0], ov[1], ov[2], ov[3]);
                *(float4*)(out + (size_t)tid * HDIM + nb + 4) = make_float4(ov[4], ov[5], ov[6], ov[7]);
            }
        }
        grid_barrier();
    }
}

// ================= launch =================
extern "C" void kernel_launch(void* const* d_in, const int* in_sizes, int n_in,
                              void* d_out, int out_size) {
    const float* x    = (const float*)d_in[0];
    const float* Wmu  = (const float*)d_in[1];
    const float* bmu  = (const float*)d_in[2];
    const float* Wgmu = (const float*)d_in[3];
    const float* bgmu = (const float*)d_in[4];
    const float* Wa   = (const float*)d_in[5];
    const float* ba   = (const float*)d_in[6];
    const float* Wga  = (const float*)d_in[7];
    const float* bga  = (const float*)d_in[8];
    float* out = (float*)d_out;

    dim3 grid_pc(HDIM / 64, (BDIM * TSTEPS) / 64);
    xa_gemm_kernel<<<grid_pc, 256>>>(x, Wa, ba);

    cudaFuncSetAttribute(recur_mma_kernel, cudaFuncAttributeMaxDynamicSharedMemorySize, SMEM_TOTAL);
    recur_mma_kernel<<<NCTA, THREADS, SMEM_TOTAL>>>(Wmu, bmu, Wgmu, bgmu, Wga, bga, out);
}

// round 8
// speedup vs baseline: 2.3641x; 1.4593x over previous
#include <cuda_runtime.h>
#include <cuda_bf16.h>
#include <cstdint>

typedef unsigned long long ull;
typedef unsigned int u32;

#define HDIM 1024
#define BDIM 64
#define TSTEPS 512
#define NCTA 128
#define NB 8
#define RTHREADS 256
#define KCH 128
#define NCHUNK 8

// recur smem (relative to 1024B-aligned base)
#define OFF_WHI 0
#define OFF_WLO 49152
#define OFF_H   98304              // + buf*32768 + part*16384
#define OFF_D   163840
#define SMEM_USED 170496
#define SMEM_TOTAL (SMEM_USED + 1024)
#define DS_STRIDE 26

// xa smem per buffer: Ahi 16K | Alo 16K | Bhi 8K | Blo 8K
#define XA_ALO 16384
#define XA_BHI 32768
#define XA_BLO 40960
#define XA_BUF 49152
#define XA_SMEM (2 * XA_BUF + 1024)

__device__ float g_A[(size_t)TSTEPS * BDIM * HDIM];          // [T][B][H]
__device__ __nv_bfloat16 g_xh[(size_t)BDIM * TSTEPS * HDIM];
__device__ __nv_bfloat16 g_xl[(size_t)BDIM * TSTEPS * HDIM];
__device__ __nv_bfloat16 g_wh[HDIM * HDIM];
__device__ __nv_bfloat16 g_wl[HDIM * HDIM];
__device__ __nv_bfloat16 g_hh[2][BDIM * HDIM];
__device__ __nv_bfloat16 g_hl[2][BDIM * HDIM];
__device__ u32 g_ready[8];

// ---------------- helpers ----------------
__device__ __forceinline__ u32 smem_u32(const void* p) {
    u32 a;
    asm("{ .reg .u64 t; cvta.to.shared.u64 t, %1; cvt.u32.u64 %0, t; }" : "=r"(a) : "l"(p));
    return a;
}
__device__ __forceinline__ void ldsm_x4(u32 a, u32& r0, u32& r1, u32& r2, u32& r3) {
    asm volatile("ldmatrix.sync.aligned.m8n8.x4.shared.b16 {%0,%1,%2,%3}, [%4];"
                 : "=r"(r0), "=r"(r1), "=r"(r2), "=r"(r3) : "r"(a));
}
__device__ __forceinline__ void ldsm_x2(u32 a, u32& r0, u32& r1) {
    asm volatile("ldmatrix.sync.aligned.m8n8.x2.shared.b16 {%0,%1}, [%2];"
                 : "=r"(r0), "=r"(r1) : "r"(a));
}
__device__ __forceinline__ void mma_bf16(float* c, u32 a0, u32 a1, u32 a2, u32 a3, u32 b0, u32 b1) {
    asm volatile(
        "mma.sync.aligned.m16n8k16.row.col.f32.bf16.bf16.f32 "
        "{%0,%1,%2,%3}, {%4,%5,%6,%7}, {%8,%9}, {%0,%1,%2,%3};"
        : "+f"(c[0]), "+f"(c[1]), "+f"(c[2]), "+f"(c[3])
        : "r"(a0), "r"(a1), "r"(a2), "r"(a3), "r"(b0), "r"(b1));
}
__device__ __forceinline__ void cpa16(u32 d, const void* s) {
    asm volatile("cp.async.cg.shared.global [%0], [%1], 16;" :: "r"(d), "l"(s) : "memory");
}
#define CP_COMMIT() asm volatile("cp.async.commit_group;" ::: "memory")
__device__ __forceinline__ unsigned short f2bf(float f) { return __bfloat16_as_ushort(__float2bfloat16(f)); }
__device__ __forceinline__ float bf2f(unsigned short s) { return __bfloat162float(__ushort_as_bfloat16(s)); }
__device__ __forceinline__ float sigf(float x) { return 1.0f / (1.0f + __expf(-x)); }
__device__ __forceinline__ u32 ld_acq(const u32* p) {
    u32 v;
    asm volatile("ld.acquire.gpu.global.u32 %0, [%1];" : "=r"(v) : "l"(p) : "memory");
    return v;
}
__device__ __forceinline__ void wait_cnt(int c, u32 need) {
    const u32* p = &g_ready[c];
    while (ld_acq(p) < need) { __nanosleep(40); }
}
// swizzled byte offset in a [rows][64] bf16 tile (128B rows, 8-row 1KB groups)
__device__ __forceinline__ u32 swz64(int row, int k) {
    u32 b = (u32)(row >> 3) * 1024u + (u32)(row & 7) * 128u + (u32)(k & 63) * 2u;
    return b ^ ((u32)(row & 7) << 4);
}

// ================= Kernel 0: fp32 -> bf16 hi/lo convert (+ zero counters) =================
__global__ void __launch_bounds__(256) conv_kernel(
    const float* __restrict__ x, const float* __restrict__ wa)
{
    if (blockIdx.x == 0 && threadIdx.x < 8) g_ready[threadIdx.x] = 0;
    const int XN4 = (BDIM * TSTEPS * HDIM) / 4, WN4 = (HDIM * HDIM) / 4;
    for (int i = blockIdx.x * blockDim.x + threadIdx.x; i < XN4 + WN4;
         i += gridDim.x * blockDim.x) {
        float4 v = (i < XN4) ? ((const float4*)x)[i] : ((const float4*)wa)[i - XN4];
        float f[4] = {v.x, v.y, v.z, v.w};
        unsigned short h[4], l[4];
#pragma unroll
        for (int j = 0; j < 4; j++) { h[j] = f2bf(f[j]); l[j] = f2bf(f[j] - bf2f(h[j])); }
        uint2 ph = make_uint2((u32)h[0] | ((u32)h[1] << 16), (u32)h[2] | ((u32)h[3] << 16));
        uint2 pl = make_uint2((u32)l[0] | ((u32)l[1] << 16), (u32)l[2] | ((u32)l[3] << 16));
        if (i < XN4) { ((uint2*)g_xh)[i] = ph; ((uint2*)g_xl)[i] = pl; }
        else         { ((uint2*)g_wh)[i - XN4] = ph; ((uint2*)g_wl)[i - XN4] = pl; }
    }
}

// ================= Kernel 1: A = x @ Wa^T + ba via mma.sync =================
// grid (16 n-blocks, 256 m-blocks), 256 thr, tiles M=128 N=64 Kc=64, cp.async double-buffered
__global__ void __launch_bounds__(256, 2) xa_mma_kernel(const float* __restrict__ ba)
{
    extern __shared__ char xsm[];
    u32 base = (smem_u32(xsm) + 1023u) & ~1023u;
    const int tid = threadIdx.x, wid = tid >> 5, lan = tid & 31;
    const int nb64 = blockIdx.x * 64, mb = blockIdx.y;

    int srcA[4]; u32 dstA[4];
#pragma unroll
    for (int j = 0; j < 4; j++) {
        int e = tid + j * 256, row = e >> 3, k8 = (e & 7) * 8;
        srcA[j] = (mb * 128 + row) * HDIM + k8;
        dstA[j] = swz64(row, k8);
    }
    int srcB[2]; u32 dstB[2];
#pragma unroll
    for (int j = 0; j < 2; j++) {
        int e = tid + j * 256, row = e >> 3, k8 = (e & 7) * 8;
        srcB[j] = (nb64 + row) * HDIM + k8;
        dstB[j] = swz64(row, k8);
    }
    const int arow = wid * 16 + (lan & 15), acb = (lan >> 4) * 8;
    u32 aoff[4];
#pragma unroll
    for (int k16 = 0; k16 < 4; k16++) aoff[k16] = swz64(arow, k16 * 16 + acb);
    const int grp = lan >> 3;
    u32 boff[4][4];
#pragma unroll
    for (int jp = 0; jp < 4; jp++) {
        int nrow = (2 * jp + (grp >> 1)) * 8 + (lan & 7);
        int kc8 = (grp & 1) * 8;
#pragma unroll
        for (int k16 = 0; k16 < 4; k16++) boff[jp][k16] = swz64(nrow, k16 * 16 + kc8);
    }

    float c[32];
#pragma unroll
    for (int i = 0; i < 32; i++) c[i] = 0.0f;

#define XA_STAGE(bb, so) do {                                             \
    _Pragma("unroll")                                                     \
    for (int j = 0; j < 4; j++) {                                         \
        cpa16((bb) + dstA[j], g_xh + srcA[j] + (so));                     \
        cpa16((bb) + XA_ALO + dstA[j], g_xl + srcA[j] + (so));            \
    }                                                                     \
    _Pragma("unroll")                                                     \
    for (int j = 0; j < 2; j++) {                                         \
        cpa16((bb) + XA_BHI + dstB[j], g_wh + srcB[j] + (so));            \
        cpa16((bb) + XA_BLO + dstB[j], g_wl + srcB[j] + (so));            \
    }                                                                     \
    CP_COMMIT(); } while (0)

    XA_STAGE(base, 0);
    for (int kc = 0; kc < 16; kc++) {
        if (kc < 15) {
            XA_STAGE(base + ((kc + 1) & 1) * XA_BUF, (kc + 1) * 64);
            asm volatile("cp.async.wait_group 1;" ::: "memory");
        } else {
            asm volatile("cp.async.wait_group 0;" ::: "memory");
        }
        __syncthreads();
        const u32 ah = base + (kc & 1) * XA_BUF;
        const u32 al = ah + XA_ALO, bh = ah + XA_BHI, bl = ah + XA_BLO;
#pragma unroll
        for (int k16 = 0; k16 < 4; k16++) {
            u32 a0, a1, a2, a3, l0, l1, l2, l3;
            ldsm_x4(ah + aoff[k16], a0, a1, a2, a3);
            ldsm_x4(al + aoff[k16], l0, l1, l2, l3);
#pragma unroll
            for (int jp = 0; jp < 4; jp++) {
                u32 h0, h1, h2, h3, q0, q1, q2, q3;
                ldsm_x4(bh + boff[jp][k16], h0, h1, h2, h3);
                ldsm_x4(bl + boff[jp][k16], q0, q1, q2, q3);
                float* c0 = c + (2 * jp) * 4;
                float* c1 = c + (2 * jp + 1) * 4;
                mma_bf16(c0, a0, a1, a2, a3, h0, h1);
                mma_bf16(c0, a0, a1, a2, a3, q0, q1);
                mma_bf16(c0, l0, l1, l2, l3, h0, h1);
                mma_bf16(c1, a0, a1, a2, a3, h2, h3);
                mma_bf16(c1, a0, a1, a2, a3, q2, q3);
                mma_bf16(c1, l0, l1, l2, l3, h2, h3);
            }
        }
        __syncthreads();
    }
    // epilogue: add ba, scatter to g_A[t][b][n]  (GEMM row = b*512 + t)
#pragma unroll
    for (int nt = 0; nt < 8; nt++) {
        int col = nb64 + nt * 8 + (lan & 3) * 2;
        float2 bav = *(const float2*)(ba + col);
        int r0 = mb * 128 + wid * 16 + (lan >> 2);
        *(float2*)&g_A[((size_t)(r0 & 511) * BDIM + (r0 >> 9)) * HDIM + col] =
            make_float2(c[nt * 4 + 0] + bav.x, c[nt * 4 + 1] + bav.y);
        int r1 = r0 + 8;
        *(float2*)&g_A[((size_t)(r1 & 511) * BDIM + (r1 >> 9)) * HDIM + col] =
            make_float2(c[nt * 4 + 2] + bav.x, c[nt * 4 + 3] + bav.y);
    }
}

// ================= Kernel 2: persistent recurrence, producer/consumer split =================
__global__ void __launch_bounds__(RTHREADS, 1) recur_mma_kernel(
    const float* __restrict__ Wmu,  const float* __restrict__ bmu,
    const float* __restrict__ Wgmu, const float* __restrict__ bgmu,
    const float* __restrict__ Wga,  const float* __restrict__ bga,
    float* __restrict__ out)
{
    extern __shared__ char smem_raw[];
    u32 raw_base = smem_u32(smem_raw);
    u32 abase = (raw_base + 1023u) & ~1023u;
    char* sm = smem_raw + (abase - raw_base);

    const int tid = threadIdx.x, wid = tid >> 5, lan = tid & 31;
    const int cta = blockIdx.x, nb = cta * NB;

    // ---- stage weights (resident all 512 steps): r = g*8+nl, SW128 swizzled ----
    for (int u = tid; u < 24 * 128; u += RTHREADS) {
        int r = u >> 7, k = (u & 127) * 8;
        int g = r >> 3, nl = r & 7;
        const float* wp = (g == 0 ? Wmu : (g == 1 ? Wgmu : Wga)) + (size_t)(nb + nl) * HDIM + k;
        float4 v0 = *(const float4*)wp;
        float4 v1 = *(const float4*)(wp + 4);
        float vv[8] = {v0.x, v0.y, v0.z, v0.w, v1.x, v1.y, v1.z, v1.w};
        u32 hw[4], lw[4];
#pragma unroll
        for (int i = 0; i < 4; i++) {
            unsigned short h0 = f2bf(vv[2*i]),   h1 = f2bf(vv[2*i+1]);
            unsigned short l0 = f2bf(vv[2*i]   - bf2f(h0));
            unsigned short l1 = f2bf(vv[2*i+1] - bf2f(h1));
            hw[i] = (u32)h0 | ((u32)h1 << 16);
            lw[i] = (u32)l0 | ((u32)l1 << 16);
        }
        u32 byte = (u32)(k >> 6) * 3072u + (u32)g * 1024u + (u32)(r & 7) * 128u + (u32)(k & 63) * 2u;
        u32 sw = byte ^ ((u32)(r & 7) << 4);
        *(uint4*)(sm + OFF_WHI + sw) = make_uint4(hw[0], hw[1], hw[2], hw[3]);
        *(uint4*)(sm + OFF_WLO + sw) = make_uint4(lw[0], lw[1], lw[2], lw[3]);
    }
    if (tid < 64) {   // h0 = 0
        uint4 z = make_uint4(0, 0, 0, 0);
        *(uint4*)&g_hh[0][tid * HDIM + nb] = z;
        *(uint4*)&g_hl[0][tid * HDIM + nb] = z;
    }
    __syncthreads();
    if (tid == 0) { __threadfence(); atomicAdd(&g_ready[cta >> 4], 1u); }  // h0 produced

    // consumer (warps 0-3) ldmatrix offsets
    const int carow = wid * 16 + (lan & 15);
    const int aklp = (lan >> 4) * 8;
    const int b7 = lan & 7, bklp = ((lan >> 3) & 1) * 8;
    u32 a_off[8], b_inn[8];
#pragma unroll
    for (int kl = 0; kl < 8; kl++) {
        int kcol = kl * 16 + aklp;
        a_off[kl] = ((u32)(kcol >> 6) * 8192u + (u32)(carow >> 3) * 1024u +
                     (u32)(carow & 7) * 128u + (u32)(kcol & 63) * 2u) ^ ((u32)(carow & 7) << 4);
        int bc = kl * 16 + bklp;
        b_inn[kl] = ((u32)(bc >> 6) * 3072u + (u32)b7 * 128u + (u32)(bc & 63) * 2u) ^ ((u32)b7 << 4);
    }
    const u32 hsb = abase + OFF_H, whib = abase + OFF_WHI, wlob = abase + OFF_WLO;
    float* ds = (float*)(sm + OFF_D);

    // producer (warps 4-7) offsets: 128 threads stage 64x128 hi+lo per chunk
    const int ptid = tid & 127;
    int srcOff[8]; u32 dstOff[8];
#pragma unroll
    for (int j = 0; j < 8; j++) {
        int e = ptid + j * 128, row = e >> 4, k = (e & 15) * 8;
        srcOff[j] = row * HDIM + k;
        dstOff[j] = ((u32)(k >> 6) * 8192u + (u32)(row >> 3) * 1024u +
                     (u32)(row & 7) * 128u + (u32)(k & 63) * 2u) ^ ((u32)(row & 7) << 4);
    }

    float cb_mu[8], cb_gm[8], cb_ga[8];
#pragma unroll
    for (int i = 0; i < 8; i++) {
        cb_mu[i] = bmu[nb + i]; cb_gm[i] = bgmu[nb + i]; cb_ga[i] = bga[nb + i];
    }

    // producer prologue: chunk 0 of h_0
    uint4 rh[8], rl[8];
    if (wid >= 4) {
        wait_cnt(0, 16u);
#pragma unroll
        for (int j = 0; j < 8; j++) {
            rh[j] = __ldcg((const uint4*)(g_hh[0] + srcOff[j]));
            rl[j] = __ldcg((const uint4*)(g_hl[0] + srcOff[j]));
        }
    }

    for (int t = 0; t < TSTEPS; t++) {
        float c[12];
#pragma unroll
        for (int i = 0; i < 12; i++) c[i] = 0.0f;
        float4 ga0 = make_float4(0, 0, 0, 0), ga1 = ga0;

        for (int kc = 0; kc < NCHUNK; kc++) {
            const int buf = kc & 1;
            __syncthreads();                         // buffer free
            if (wid >= 4) {
                char* hb = sm + OFF_H + buf * 32768;
#pragma unroll
                for (int j = 0; j < 8; j++) {
                    *(uint4*)(hb + dstOff[j])         = rh[j];
                    *(uint4*)(hb + 16384 + dstOff[j]) = rl[j];
                }
            }
            __syncthreads();                         // staged visible
            if (wid >= 4) {
                if (kc < NCHUNK - 1) {               // next chunk of h_t
                    wait_cnt(kc + 1, 16u * (u32)(t + 1));
                    const __nv_bfloat16* hh = g_hh[t & 1];
                    const __nv_bfloat16* hl = g_hl[t & 1];
                    int so = (kc + 1) * KCH;
#pragma unroll
                    for (int j = 0; j < 8; j++) {
                        rh[j] = __ldcg((const uint4*)(hh + srcOff[j] + so));
                        rl[j] = __ldcg((const uint4*)(hl + srcOff[j] + so));
                    }
                } else if (t < TSTEPS - 1) {         // chunk 0 of h_{t+1}
                    wait_cnt(0, 16u * (u32)(t + 2));
                    const __nv_bfloat16* hh = g_hh[(t + 1) & 1];
                    const __nv_bfloat16* hl = g_hl[(t + 1) & 1];
#pragma unroll
                    for (int j = 0; j < 8; j++) {
                        rh[j] = __ldcg((const uint4*)(hh + srcOff[j]));
                        rl[j] = __ldcg((const uint4*)(hl + srcOff[j]));
                    }
                }
            } else {
                if (kc == 6 && tid < 64) {           // prefetch g_A for epilogue
                    const float* ap = g_A + ((size_t)t * BDIM + tid) * HDIM + nb;
                    ga0 = __ldcg((const float4*)ap);
                    ga1 = __ldcg((const float4*)(ap + 4));
                }
                const u32 ahb = hsb + buf * 32768, alb = ahb + 16384;
                const u32 wko = (u32)kc * 6144u;
#pragma unroll
                for (int kl = 0; kl < 8; kl++) {
                    u32 ah0, ah1, ah2, ah3, al0, al1, al2, al3;
                    ldsm_x4(ahb + a_off[kl], ah0, ah1, ah2, ah3);
                    ldsm_x4(alb + a_off[kl], al0, al1, al2, al3);
#pragma unroll
                    for (int g = 0; g < 3; g++) {
                        u32 wo = wko + (u32)g * 1024u + b_inn[kl];
                        u32 bh0, bh1, bl0, bl1;
                        ldsm_x2(whib + wo, bh0, bh1);
                        ldsm_x2(wlob + wo, bl0, bl1);
                        mma_bf16(c + g * 4, ah0, ah1, ah2, ah3, bh0, bh1);
                        mma_bf16(c + g * 4, ah0, ah1, ah2, ah3, bl0, bl1);
                        mma_bf16(c + g * 4, al0, al1, al2, al3, bh0, bh1);
                    }
                }
            }
        }

        // ---- step end (consumer warps only; producers run ahead into t+1) ----
        if (wid < 4) {
            int r0 = wid * 16 + (lan >> 2), cc = (lan & 3) * 2;
#pragma unroll
            for (int g = 0; g < 3; g++) {
                *(float2*)&ds[r0 * DS_STRIDE + g * 8 + cc]       = make_float2(c[g*4+0], c[g*4+1]);
                *(float2*)&ds[(r0 + 8) * DS_STRIDE + g * 8 + cc] = make_float2(c[g*4+2], c[g*4+3]);
            }
            asm volatile("bar.sync 1, 128;" ::: "memory");
            if (tid < 64) {
                const float* drow = ds + tid * DS_STRIDE;
                float av[8] = {ga0.x, ga0.y, ga0.z, ga0.w, ga1.x, ga1.y, ga1.z, ga1.w};
                float ov[8];
#pragma unroll
                for (int i = 0; i < 8; i++) {
                    float mu = drow[i] + cb_mu[i];
                    float gm = drow[8 + i] + cb_gm[i];
                    float ga = drow[16 + i] + cb_ga[i];
                    ov[i] = mu * sigf(gm) + av[i] * sigf(ga);
                }
                u32 hw[4], lw[4];
#pragma unroll
                for (int i = 0; i < 4; i++) {
                    unsigned short h0 = f2bf(ov[2*i]),   h1 = f2bf(ov[2*i+1]);
                    unsigned short l0 = f2bf(ov[2*i]   - bf2f(h0));
                    unsigned short l1 = f2bf(ov[2*i+1] - bf2f(h1));
                    hw[i] = (u32)h0 | ((u32)h1 << 16);
                    lw[i] = (u32)l0 | ((u32)l1 << 16);
                }
                __stcg((uint4*)&g_hh[(t + 1) & 1][tid * HDIM + nb], make_uint4(hw[0], hw[1], hw[2], hw[3]));
                __stcg((uint4*)&g_hl[(t + 1) & 1][tid * HDIM + nb], make_uint4(lw[0], lw[1], lw[2], lw[3]));
                if (t == TSTEPS - 1) {
                    *(float4*)(out + (size_t)tid * HDIM + nb)     = make_float4(ov[0], ov[1], ov[2], ov[3]);
                    *(float4*)(out + (size_t)tid * HDIM + nb + 4) = make_float4(ov[4], ov[5], ov[6], ov[7]);
                }
            }
            asm volatile("bar.sync 1, 128;" ::: "memory");
            if (tid == 0) { __threadfence(); atomicAdd(&g_ready[cta >> 4], 1u); }
        }
    }
}

// ================= launch =================
extern "C" void kernel_launch(void* const* d_in, const int* in_sizes, int n_in,
                              void* d_out, int out_size) {
    const float* x    = (const float*)d_in[0];
    const float* Wmu  = (const float*)d_in[1];
    const float* bmu  = (const float*)d_in[2];
    const float* Wgmu = (const float*)d_in[3];
    const float* bgmu = (const float*)d_in[4];
    const float* Wa   = (const float*)d_in[5];
    const float* ba   = (const float*)d_in[6];
    const float* Wga  = (const float*)d_in[7];
    const float* bga  = (const float*)d_in[8];
    float* out = (float*)d_out;

    conv_kernel<<<2048, 256>>>(x, Wa);

    cudaFuncSetAttribute(xa_mma_kernel, cudaFuncAttributeMaxDynamicSharedMemorySize, XA_SMEM);
    xa_mma_kernel<<<dim3(16, 256), 256, XA_SMEM>>>(ba);

    cudaFuncSetAttribute(recur_mma_kernel, cudaFuncAttributeMaxDynamicSharedMemorySize, SMEM_TOTAL);
    recur_mma_kernel<<<NCTA, RTHREADS, SMEM_TOTAL>>>(Wmu, bmu, Wgmu, bgmu, Wga, bga, out);
}

// round 9
// speedup vs baseline: 2.6579x; 1.1243x over previous
#include <cuda_runtime.h>
#include <cuda_bf16.h>
#include <cstdint>

typedef unsigned long long ull;
typedef unsigned int u32;

#define HDIM 1024
#define BDIM 64
#define TSTEPS 512
#define NCTA 128
#define NB 8
#define RTHREADS 256
#define KCH 128
#define NCHUNK 8
#define NTOT (TSTEPS * NCHUNK)

// recur smem (relative to 1024B-aligned base)
#define OFF_WHI 0
#define OFF_WLO 49152
#define OFF_RING 98304             // 3 slots x 32768 (hi 16K + lo 16K)
#define SLOT_SZ 32768
#define OFF_D   196608
#define SMEM_USED 203264
#define SMEM_TOTAL (SMEM_USED + 1024)
#define DS_STRIDE 26

// xa smem per buffer: Ahi 16K | Alo 16K | Bhi 8K | Blo 8K
#define XA_ALO 16384
#define XA_BHI 32768
#define XA_BLO 40960
#define XA_BUF 49152
#define XA_SMEM (2 * XA_BUF + 1024)

__device__ float g_A[(size_t)TSTEPS * BDIM * HDIM];          // [T][B][H]
__device__ __nv_bfloat16 g_xh[(size_t)BDIM * TSTEPS * HDIM];
__device__ __nv_bfloat16 g_xl[(size_t)BDIM * TSTEPS * HDIM];
__device__ __nv_bfloat16 g_wh[HDIM * HDIM];
__device__ __nv_bfloat16 g_wl[HDIM * HDIM];
__device__ __nv_bfloat16 g_hh[2][BDIM * HDIM];
__device__ __nv_bfloat16 g_hl[2][BDIM * HDIM];
__device__ u32 g_ready[8][32];                               // one 128B line per counter

// ---------------- helpers ----------------
__device__ __forceinline__ u32 smem_u32(const void* p) {
    u32 a;
    asm("{ .reg .u64 t; cvta.to.shared.u64 t, %1; cvt.u32.u64 %0, t; }" : "=r"(a) : "l"(p));
    return a;
}
__device__ __forceinline__ void ldsm_x4(u32 a, u32& r0, u32& r1, u32& r2, u32& r3) {
    asm volatile("ldmatrix.sync.aligned.m8n8.x4.shared.b16 {%0,%1,%2,%3}, [%4];"
                 : "=r"(r0), "=r"(r1), "=r"(r2), "=r"(r3) : "r"(a));
}
__device__ __forceinline__ void ldsm_x2(u32 a, u32& r0, u32& r1) {
    asm volatile("ldmatrix.sync.aligned.m8n8.x2.shared.b16 {%0,%1}, [%2];"
                 : "=r"(r0), "=r"(r1) : "r"(a));
}
__device__ __forceinline__ void mma_bf16(float* c, u32 a0, u32 a1, u32 a2, u32 a3, u32 b0, u32 b1) {
    asm volatile(
        "mma.sync.aligned.m16n8k16.row.col.f32.bf16.bf16.f32 "
        "{%0,%1,%2,%3}, {%4,%5,%6,%7}, {%8,%9}, {%0,%1,%2,%3};"
        : "+f"(c[0]), "+f"(c[1]), "+f"(c[2]), "+f"(c[3])
        : "r"(a0), "r"(a1), "r"(a2), "r"(a3), "r"(b0), "r"(b1));
}
__device__ __forceinline__ void cpa16(u32 d, const void* s) {
    asm volatile("cp.async.cg.shared.global [%0], [%1], 16;" :: "r"(d), "l"(s) : "memory");
}
#define CP_COMMIT() asm volatile("cp.async.commit_group;" ::: "memory")
#define CP_WAIT0()  asm volatile("cp.async.wait_group 0;" ::: "memory")
#define CP_WAIT1()  asm volatile("cp.async.wait_group 1;" ::: "memory")
__device__ __forceinline__ void bar_sync_id(int id, int cnt) {
    asm volatile("bar.sync %0, %1;" :: "r"(id), "r"(cnt) : "memory");
}
__device__ __forceinline__ void bar_arrive_id(int id, int cnt) {
    asm volatile("bar.arrive %0, %1;" :: "r"(id), "r"(cnt) : "memory");
}
__device__ __forceinline__ unsigned short f2bf(float f) { return __bfloat16_as_ushort(__float2bfloat16(f)); }
__device__ __forceinline__ float bf2f(unsigned short s) { return __bfloat162float(__ushort_as_bfloat16(s)); }
__device__ __forceinline__ float sigf(float x) { return 1.0f / (1.0f + __expf(-x)); }
__device__ __forceinline__ u32 ld_acq(const u32* p) {
    u32 v;
    asm volatile("ld.acquire.gpu.global.u32 %0, [%1];" : "=r"(v) : "l"(p) : "memory");
    return v;
}
__device__ __forceinline__ void wait_cnt_w(int c, u32 need, int lane) {
    if (lane == 0) {
        const u32* p = &g_ready[c][0];
        while (ld_acq(p) < need) { __nanosleep(40); }
    }
    __syncwarp();
}
__device__ __forceinline__ u32 swz64(int row, int k) {
    u32 b = (u32)(row >> 3) * 1024u + (u32)(row & 7) * 128u + (u32)(k & 63) * 2u;
    return b ^ ((u32)(row & 7) << 4);
}

// ================= Kernel 0: fp32 -> bf16 hi/lo convert (+ zero counters) =================
__global__ void __launch_bounds__(256) conv_kernel(
    const float* __restrict__ x, const float* __restrict__ wa)
{
    if (blockIdx.x == 0 && threadIdx.x < 8) g_ready[threadIdx.x][0] = 0;
    const int XN4 = (BDIM * TSTEPS * HDIM) / 4, WN4 = (HDIM * HDIM) / 4;
    for (int i = blockIdx.x * blockDim.x + threadIdx.x; i < XN4 + WN4;
         i += gridDim.x * blockDim.x) {
        float4 v = (i < XN4) ? ((const float4*)x)[i] : ((const float4*)wa)[i - XN4];
        float f[4] = {v.x, v.y, v.z, v.w};
        unsigned short h[4], l[4];
#pragma unroll
        for (int j = 0; j < 4; j++) { h[j] = f2bf(f[j]); l[j] = f2bf(f[j] - bf2f(h[j])); }
        uint2 ph = make_uint2((u32)h[0] | ((u32)h[1] << 16), (u32)h[2] | ((u32)h[3] << 16));
        uint2 pl = make_uint2((u32)l[0] | ((u32)l[1] << 16), (u32)l[2] | ((u32)l[3] << 16));
        if (i < XN4) { ((uint2*)g_xh)[i] = ph; ((uint2*)g_xl)[i] = pl; }
        else         { ((uint2*)g_wh)[i - XN4] = ph; ((uint2*)g_wl)[i - XN4] = pl; }
    }
}

// ================= Kernel 1: A = x @ Wa^T + ba via mma.sync (unchanged) =================
__global__ void __launch_bounds__(256, 2) xa_mma_kernel(const float* __restrict__ ba)
{
    extern __shared__ char xsm[];
    u32 base = (smem_u32(xsm) + 1023u) & ~1023u;
    const int tid = threadIdx.x, wid = tid >> 5, lan = tid & 31;
    const int nb64 = blockIdx.x * 64, mb = blockIdx.y;

    int srcA[4]; u32 dstA[4];
#pragma unroll
    for (int j = 0; j < 4; j++) {
        int e = tid + j * 256, row = e >> 3, k8 = (e & 7) * 8;
        srcA[j] = (mb * 128 + row) * HDIM + k8;
        dstA[j] = swz64(row, k8);
    }
    int srcB[2]; u32 dstB[2];
#pragma unroll
    for (int j = 0; j < 2; j++) {
        int e = tid + j * 256, row = e >> 3, k8 = (e & 7) * 8;
        srcB[j] = (nb64 + row) * HDIM + k8;
        dstB[j] = swz64(row, k8);
    }
    const int arow = wid * 16 + (lan & 15), acb = (lan >> 4) * 8;
    u32 aoff[4];
#pragma unroll
    for (int k16 = 0; k16 < 4; k16++) aoff[k16] = swz64(arow, k16 * 16 + acb);
    const int grp = lan >> 3;
    u32 boff[4][4];
#pragma unroll
    for (int jp = 0; jp < 4; jp++) {
        int nrow = (2 * jp + (grp >> 1)) * 8 + (lan & 7);
        int kc8 = (grp & 1) * 8;
#pragma unroll
        for (int k16 = 0; k16 < 4; k16++) boff[jp][k16] = swz64(nrow, k16 * 16 + kc8);
    }

    float c[32];
#pragma unroll
    for (int i = 0; i < 32; i++) c[i] = 0.0f;

#define XA_STAGE(bb, so) do {                                             \
    _Pragma("unroll")                                                     \
    for (int j = 0; j < 4; j++) {                                         \
        cpa16((bb) + dstA[j], g_xh + srcA[j] + (so));                     \
        cpa16((bb) + XA_ALO + dstA[j], g_xl + srcA[j] + (so));            \
    }                                                                     \
    _Pragma("unroll")                                                     \
    for (int j = 0; j < 2; j++) {                                         \
        cpa16((bb) + XA_BHI + dstB[j], g_wh + srcB[j] + (so));            \
        cpa16((bb) + XA_BLO + dstB[j], g_wl + srcB[j] + (so));            \
    }                                                                     \
    CP_COMMIT(); } while (0)

    XA_STAGE(base, 0);
    for (int kc = 0; kc < 16; kc++) {
        if (kc < 15) {
            XA_STAGE(base + ((kc + 1) & 1) * XA_BUF, (kc + 1) * 64);
            CP_WAIT1();
        } else {
            CP_WAIT0();
        }
        __syncthreads();
        const u32 ah = base + (kc & 1) * XA_BUF;
        const u32 al = ah + XA_ALO, bh = ah + XA_BHI, bl = ah + XA_BLO;
#pragma unroll
        for (int k16 = 0; k16 < 4; k16++) {
            u32 a0, a1, a2, a3, l0, l1, l2, l3;
            ldsm_x4(ah + aoff[k16], a0, a1, a2, a3);
            ldsm_x4(al + aoff[k16], l0, l1, l2, l3);
#pragma unroll
            for (int jp = 0; jp < 4; jp++) {
                u32 h0, h1, h2, h3, q0, q1, q2, q3;
                ldsm_x4(bh + boff[jp][k16], h0, h1, h2, h3);
                ldsm_x4(bl + boff[jp][k16], q0, q1, q2, q3);
                float* c0 = c + (2 * jp) * 4;
                float* c1 = c + (2 * jp + 1) * 4;
                mma_bf16(c0, a0, a1, a2, a3, h0, h1);
                mma_bf16(c0, a0, a1, a2, a3, q0, q1);
                mma_bf16(c0, l0, l1, l2, l3, h0, h1);
                mma_bf16(c1, a0, a1, a2, a3, h2, h3);
                mma_bf16(c1, a0, a1, a2, a3, q2, q3);
                mma_bf16(c1, l0, l1, l2, l3, h2, h3);
            }
        }
        __syncthreads();
    }
#pragma unroll
    for (int nt = 0; nt < 8; nt++) {
        int col = nb64 + nt * 8 + (lan & 3) * 2;
        float2 bav = *(const float2*)(ba + col);
        int r0 = mb * 128 + wid * 16 + (lan >> 2);
        *(float2*)&g_A[((size_t)(r0 & 511) * BDIM + (r0 >> 9)) * HDIM + col] =
            make_float2(c[nt * 4 + 0] + bav.x, c[nt * 4 + 1] + bav.y);
        int r1 = r0 + 8;
        *(float2*)&g_A[((size_t)(r1 & 511) * BDIM + (r1 >> 9)) * HDIM + col] =
            make_float2(c[nt * 4 + 2] + bav.x, c[nt * 4 + 3] + bav.y);
    }
}

// ================= Kernel 2: persistent recurrence, cp.async ring =================
// Warps 0-3 consumers (MMA+epilogue), warps 4-7 producers (cp.async staging).
// FULL barriers ids 2..4 (producer arrive, consumer sync); FREE ids 5..7 (reverse).
__global__ void __launch_bounds__(RTHREADS, 1) recur_mma_kernel(
    const float* __restrict__ Wmu,  const float* __restrict__ bmu,
    const float* __restrict__ Wgmu, const float* __restrict__ bgmu,
    const float* __restrict__ Wga,  const float* __restrict__ bga,
    float* __restrict__ out)
{
    extern __shared__ char smem_raw[];
    u32 raw_base = smem_u32(smem_raw);
    u32 abase = (raw_base + 1023u) & ~1023u;
    char* sm = smem_raw + (abase - raw_base);

    const int tid = threadIdx.x, wid = tid >> 5, lan = tid & 31;
    const int cta = blockIdx.x, nb = cta * NB;

    // ---- stage weights (resident all 512 steps) ----
    for (int u = tid; u < 24 * 128; u += RTHREADS) {
        int r = u >> 7, k = (u & 127) * 8;
        int g = r >> 3, nl = r & 7;
        const float* wp = (g == 0 ? Wmu : (g == 1 ? Wgmu : Wga)) + (size_t)(nb + nl) * HDIM + k;
        float4 v0 = *(const float4*)wp;
        float4 v1 = *(const float4*)(wp + 4);
        float vv[8] = {v0.x, v0.y, v0.z, v0.w, v1.x, v1.y, v1.z, v1.w};
        u32 hw[4], lw[4];
#pragma unroll
        for (int i = 0; i < 4; i++) {
            unsigned short h0 = f2bf(vv[2*i]),   h1 = f2bf(vv[2*i+1]);
            unsigned short l0 = f2bf(vv[2*i]   - bf2f(h0));
            unsigned short l1 = f2bf(vv[2*i+1] - bf2f(h1));
            hw[i] = (u32)h0 | ((u32)h1 << 16);
            lw[i] = (u32)l0 | ((u32)l1 << 16);
        }
        u32 byte = (u32)(k >> 6) * 3072u + (u32)g * 1024u + (u32)(r & 7) * 128u + (u32)(k & 63) * 2u;
        u32 sw = byte ^ ((u32)(r & 7) << 4);
        *(uint4*)(sm + OFF_WHI + sw) = make_uint4(hw[0], hw[1], hw[2], hw[3]);
        *(uint4*)(sm + OFF_WLO + sw) = make_uint4(lw[0], lw[1], lw[2], lw[3]);
    }
    if (tid < 64) {   // h0 = 0
        uint4 z = make_uint4(0, 0, 0, 0);
        *(uint4*)&g_hh[0][tid * HDIM + nb] = z;
        *(uint4*)&g_hl[0][tid * HDIM + nb] = z;
    }
    __syncthreads();
    if (tid == 0) { __threadfence(); atomicAdd(&g_ready[cta >> 4][0], 1u); }

    const u32 hsb = abase + OFF_RING, whib = abase + OFF_WHI, wlob = abase + OFF_WLO;

    if (wid >= 4) {
        // ================== PRODUCER ==================
        const int ptid = tid & 127;
        int srcOff[8]; u32 dstOff[8];
#pragma unroll
        for (int j = 0; j < 8; j++) {
            int e = ptid + j * 128, row = e >> 4, k = (e & 15) * 8;
            srcOff[j] = row * HDIM + k;
            dstOff[j] = ((u32)(k >> 6) * 8192u + (u32)(row >> 3) * 1024u +
                         (u32)(row & 7) * 128u + (u32)(k & 63) * 2u) ^ ((u32)(row & 7) << 4);
        }
#define ISSUE_CHUNK(hhp, hlp, sb, so) do {                                  \
    _Pragma("unroll")                                                       \
    for (int j = 0; j < 8; j++) {                                           \
        cpa16((sb) + dstOff[j], (hhp) + srcOff[j] + (so));                  \
        cpa16((sb) + 16384 + dstOff[j], (hlp) + srcOff[j] + (so));          \
    }                                                                       \
    CP_COMMIT(); } while (0)

        wait_cnt_w(0, 16u, lan);
        ISSUE_CHUNK(g_hh[0], g_hl[0], hsb, 0);
        wait_cnt_w(1, 16u, lan);
        ISSUE_CHUNK(g_hh[0], g_hl[0], hsb + SLOT_SZ, KCH);

        int sig = 0, sig_sl = 0, m_sl = 2;
        for (int m = 2; m <= NTOT; m++) {
            if ((m & 7) == 0 || m == NTOT) {
                // drain fully and signal everything before any blocking wait
                CP_WAIT0();
                while (sig < m) {
                    bar_arrive_id(2 + sig_sl, 256);
                    sig++; if (++sig_sl == 3) sig_sl = 0;
                }
            } else {
                CP_WAIT1();
                if (sig < m - 1) {
                    bar_arrive_id(2 + sig_sl, 256);
                    sig++; if (++sig_sl == 3) sig_sl = 0;
                }
            }
            if (m == NTOT) break;
            if (m >= 3) bar_sync_id(5 + m_sl, 256);        // consumer freed chunk m-3
            int tm = m >> 3, cm = m & 7;
            wait_cnt_w(cm, 16u * (u32)(tm + 1), lan);
            const __nv_bfloat16* hh = g_hh[tm & 1];
            const __nv_bfloat16* hl = g_hl[tm & 1];
            ISSUE_CHUNK(hh, hl, hsb + (u32)m_sl * SLOT_SZ, cm * KCH);
            if (++m_sl == 3) m_sl = 0;
        }
    } else {
        // ================== CONSUMER ==================
        const int carow = wid * 16 + (lan & 15);
        const int aklp = (lan >> 4) * 8;
        const int b7 = lan & 7, bklp = ((lan >> 3) & 1) * 8;
        u32 a_off[8], b_inn[8];
#pragma unroll
        for (int kl = 0; kl < 8; kl++) {
            int kcol = kl * 16 + aklp;
            a_off[kl] = ((u32)(kcol >> 6) * 8192u + (u32)(carow >> 3) * 1024u +
                         (u32)(carow & 7) * 128u + (u32)(kcol & 63) * 2u) ^ ((u32)(carow & 7) << 4);
            int bc = kl * 16 + bklp;
            b_inn[kl] = ((u32)(bc >> 6) * 3072u + (u32)b7 * 128u + (u32)(bc & 63) * 2u) ^ ((u32)b7 << 4);
        }
        float* ds = (float*)(sm + OFF_D);
        float cb_mu[8], cb_gm[8], cb_ga[8];
#pragma unroll
        for (int i = 0; i < 8; i++) {
            cb_mu[i] = bmu[nb + i]; cb_gm[i] = bgmu[nb + i]; cb_ga[i] = bga[nb + i];
        }

        int sl = 0;
        for (int t = 0; t < TSTEPS; t++) {
            float c[12];
#pragma unroll
            for (int i = 0; i < 12; i++) c[i] = 0.0f;
            float4 ga0 = make_float4(0, 0, 0, 0), ga1 = ga0;

            for (int kc = 0; kc < NCHUNK; kc++) {
                bar_sync_id(2 + sl, 256);                   // slot full
                if (kc == 6 && tid < 64) {
                    const float* ap = g_A + ((size_t)t * BDIM + tid) * HDIM + nb;
                    ga0 = __ldcg((const float4*)ap);
                    ga1 = __ldcg((const float4*)(ap + 4));
                }
                const u32 ahb = hsb + (u32)sl * SLOT_SZ, alb = ahb + 16384;
                const u32 wko = (u32)kc * 6144u;
#pragma unroll
                for (int kl = 0; kl < 8; kl++) {
                    u32 ah0, ah1, ah2, ah3, al0, al1, al2, al3;
                    ldsm_x4(ahb + a_off[kl], ah0, ah1, ah2, ah3);
                    ldsm_x4(alb + a_off[kl], al0, al1, al2, al3);
#pragma unroll
                    for (int g = 0; g < 3; g++) {
                        u32 wo = wko + (u32)g * 1024u + b_inn[kl];
                        u32 bh0, bh1, bl0, bl1;
                        ldsm_x2(whib + wo, bh0, bh1);
                        ldsm_x2(wlob + wo, bl0, bl1);
                        mma_bf16(c + g * 4, ah0, ah1, ah2, ah3, bh0, bh1);
                        mma_bf16(c + g * 4, ah0, ah1, ah2, ah3, bl0, bl1);
                        mma_bf16(c + g * 4, al0, al1, al2, al3, bh0, bh1);
                    }
                }
                bar_arrive_id(5 + sl, 256);                 // slot free
                if (++sl == 3) sl = 0;
            }

            // ---- D exchange + epilogue ----
            int r0 = wid * 16 + (lan >> 2), cc = (lan & 3) * 2;
#pragma unroll
            for (int g = 0; g < 3; g++) {
                *(float2*)&ds[r0 * DS_STRIDE + g * 8 + cc]       = make_float2(c[g*4+0], c[g*4+1]);
                *(float2*)&ds[(r0 + 8) * DS_STRIDE + g * 8 + cc] = make_float2(c[g*4+2], c[g*4+3]);
            }
            bar_sync_id(1, 128);
            if (tid < 64) {
                const float* drow = ds + tid * DS_STRIDE;
                float av[8] = {ga0.x, ga0.y, ga0.z, ga0.w, ga1.x, ga1.y, ga1.z, ga1.w};
                float ov[8];
#pragma unroll
                for (int i = 0; i < 8; i++) {
                    float mu = drow[i] + cb_mu[i];
                    float gm = drow[8 + i] + cb_gm[i];
                    float ga = drow[16 + i] + cb_ga[i];
                    ov[i] = mu * sigf(gm) + av[i] * sigf(ga);
                }
                u32 hw[4], lw[4];
#pragma unroll
                for (int i = 0; i < 4; i++) {
                    unsigned short h0 = f2bf(ov[2*i]),   h1 = f2bf(ov[2*i+1]);
                    unsigned short l0 = f2bf(ov[2*i]   - bf2f(h0));
                    unsigned short l1 = f2bf(ov[2*i+1] - bf2f(h1));
                    hw[i] = (u32)h0 | ((u32)h1 << 16);
                    lw[i] = (u32)l0 | ((u32)l1 << 16);
                }
                __stcg((uint4*)&g_hh[(t + 1) & 1][tid * HDIM + nb], make_uint4(hw[0], hw[1], hw[2], hw[3]));
                __stcg((uint4*)&g_hl[(t + 1) & 1][tid * HDIM + nb], make_uint4(lw[0], lw[1], lw[2], lw[3]));
                if (t == TSTEPS - 1) {
                    *(float4*)(out + (size_t)tid * HDIM + nb)     = make_float4(ov[0], ov[1], ov[2], ov[3]);
                    *(float4*)(out + (size_t)tid * HDIM + nb + 4) = make_float4(ov[4], ov[5], ov[6], ov[7]);
                }
            }
            bar_sync_id(1, 128);
            if (tid == 0) { __threadfence(); atomicAdd(&g_ready[cta >> 4][0], 1u); }
        }
    }
}

// ================= launch =================
extern "C" void kernel_launch(void* const* d_in, const int* in_sizes, int n_in,
                              void* d_out, int out_size) {
    const float* x    = (const float*)d_in[0];
    const float* Wmu  = (const float*)d_in[1];
    const float* bmu  = (const float*)d_in[2];
    const float* Wgmu = (const float*)d_in[3];
    const float* bgmu = (const float*)d_in[4];
    const float* Wa   = (const float*)d_in[5];
    const float* ba   = (const float*)d_in[6];
    const float* Wga  = (const float*)d_in[7];
    const float* bga  = (const float*)d_in[8];
    float* out = (float*)d_out;

    conv_kernel<<<2048, 256>>>(x, Wa);

    cudaFuncSetAttribute(xa_mma_kernel, cudaFuncAttributeMaxDynamicSharedMemorySize, XA_SMEM);
    xa_mma_kernel<<<dim3(16, 256), 256, XA_SMEM>>>(ba);

    cudaFuncSetAttribute(recur_mma_kernel, cudaFuncAttributeMaxDynamicSharedMemorySize, SMEM_TOTAL);
    recur_mma_kernel<<<NCTA, RTHREADS, SMEM_TOTAL>>>(Wmu, bmu, Wgmu, bgmu, Wga, bga, out);
}